// round 10
// baseline (speedup 1.0000x reference)
#include <cuda_runtime.h>
#include <cuda_fp16.h>

#define BATCH 32768
#define HW 15
#define CELLS 225          // 15*15
#define PCODE 2380
#define NROWS (2 * (PCODE + 1))   // 4762 embedding rows
#define SMROW 17           // 15 + 2 halo
#define SMCOL 18           // padded (9 uint4 per row; col16 halo, col17 pad, both 0)
#define BLOCKS_PER_SM 10
#define GRID_P (148 * BLOCKS_PER_SM)   // 1480 persistent blocks
#define WARPS_PER_BLOCK 4
#define TOTAL_WARPS (GRID_P * WARPS_PER_BLOCK)

// fp16 embedding table: row = 8 halves = 16 bytes -> one LDG.128 per row
__device__ __align__(16) __half g_emb[NROWS * 8];

__global__ void __launch_bounds__(256)
emb_to_half_kernel(const float* __restrict__ W_emb) {
    int i = blockIdx.x * 256 + threadIdx.x;          // one half4 (4 floats) per thread
    if (i < NROWS * 2) {
        float4 f = __ldg((const float4*)(W_emb + (size_t)i * 4));
        __half2* dst = (__half2*)(g_emb + (size_t)i * 4);
        dst[0] = __floats2half2_rn(f.x, f.y);
        dst[1] = __floats2half2_rn(f.z, f.w);
    }
}

__device__ __forceinline__ float lrelu16(float x) {
    return x >= 0.f ? x : x * 0.0625f;
}

__device__ __forceinline__ void unpack_cell(unsigned lo, unsigned hi, float* out) {
    float2 a = __half22float2(*(__half2*)&lo);
    float2 b = __half22float2(*(__half2*)&hi);
    out[0] = a.x; out[1] = a.y; out[2] = b.x; out[3] = b.y;
}

// gather one cell's two fp16 embedding rows, emit packed policy half4 + value f32x4
__device__ __forceinline__ void gather_cell(int r0, int r1, uint2* pol,
                                            float& v4, float& v5, float& v6, float& v7) {
    uint4 e0 = __ldg((const uint4*)(g_emb + (size_t)r0 * 8));
    uint4 e1 = __ldg((const uint4*)(g_emb + (size_t)r1 * 8));
    float2 p01 = __half22float2(*(__half2*)&e0.x);
    float2 q01 = __half22float2(*(__half2*)&e1.x);
    float2 p23 = __half22float2(*(__half2*)&e0.y);
    float2 q23 = __half22float2(*(__half2*)&e1.y);
    float2 a45 = __half22float2(*(__half2*)&e0.z);
    float2 b45 = __half22float2(*(__half2*)&e1.z);
    float2 a67 = __half22float2(*(__half2*)&e0.w);
    float2 b67 = __half22float2(*(__half2*)&e1.w);
    __half2 hp0 = __floats2half2_rn(p01.x + q01.x, p01.y + q01.y);
    __half2 hp1 = __floats2half2_rn(p23.x + q23.x, p23.y + q23.y);
    *pol = make_uint2(*(unsigned*)&hp0, *(unsigned*)&hp1);
    v4 += a45.x + b45.x;
    v5 += a45.y + b45.y;
    v6 += a67.x + b67.x;
    v7 += a67.y + b67.y;
}

__global__ void __launch_bounds__(128, BLOCKS_PER_SM)
patnnue_kernel(const int* __restrict__ sparse,   // (B,12,15,15)
               const int* __restrict__ board,    // (B,2,15,15)
               const float* __restrict__ dw_w,   // (4,1,3,3)
               const float* __restrict__ dw_b,   // (4,)
               const float* __restrict__ pf_w,   // (1,4,1,1)
               const float* __restrict__ l1_w,   // (4,4)
               const float* __restrict__ l1_b,   // (4,)
               const float* __restrict__ l2_w,   // (4,4)
               const float* __restrict__ l2_b,   // (4,)
               const float* __restrict__ vf_w,   // (3,4)
               const float* __restrict__ vf_b,   // (3,)
               float* __restrict__ out_v,        // (B,3)
               float* __restrict__ out_p)        // (B,1,15,15)
{
    const int t    = threadIdx.x;
    const int w    = t >> 5;
    const int lane = t & 31;

    __shared__ __align__(16) uint2 feat_s[WARPS_PER_BLOCK][SMROW][SMCOL]; // per-warp tile
    __shared__ float4 wtap[9];               // dw weights, tap-major across channels
    __shared__ float4 wb4;                   // dw_b
    __shared__ float4 wpf4;                  // pf_w

    // ---- one-time init: zero all tiles (halo stays zero forever) + weights ----
    uint2* fz = &feat_s[0][0][0];
    for (int i = t; i < WARPS_PER_BLOCK * SMROW * SMCOL; i += 128)
        fz[i] = make_uint2(0u, 0u);
    if (t < 36) {
        float wv = __ldg(dw_w + t);
        ((float*)&wtap[t % 9])[t / 9] = wv;  // transpose to tap-major
    } else if (t == 36) {
        wb4  = __ldg((const float4*)dw_b);
    } else if (t == 37) {
        wpf4 = __ldg((const float4*)pf_w);
    }
    __syncthreads();                          // the ONLY block-wide barrier

    uint2 (*tile)[SMCOL] = feat_s[w];
    const int gw = blockIdx.x * WARPS_PER_BLOCK + w;

    for (int b = gw; b < BATCH; b += TOTAL_WARPS) {
        const int* sp = sparse + (long long)b * (12 * CELLS);
        const int* bd = board  + (long long)b * (2 * CELLS);

        // ---- phase 1: gather, lane strides cells ----
        float v4 = 0.f, v5 = 0.f, v6 = 0.f, v7 = 0.f;
        #pragma unroll
        for (int k = 0; k < 8; k++) {
            const int c = lane + 32 * k;
            if (c < CELLS) {
                const int i0 = __ldg(sp + 10 * CELLS + c);
                const int i1 = __ldg(sp + 11 * CELLS + c);
                const bool ne = (__ldg(bd + c) + __ldg(bd + CELLS + c)) > 0;
                const int r0 = ne ? PCODE : i0;
                const int r1 = (ne ? PCODE : i1) + (PCODE + 1);
                uint2 pol;
                gather_cell(r0, r1, &pol, v4, v5, v6, v7);
                tile[c / HW + 1][c % HW + 1] = pol;
            }
        }
        __syncwarp();

        // ---- phase 2: conv, 4 output cells per thread (60 slots, 2 iterations) ----
        #pragma unroll
        for (int k = 0; k < 2; k++) {
            const int slot = lane + 32 * k;
            if (slot < 60) {
                const int y  = slot >> 2;           // 0..14
                const int j  = slot & 3;            // 0..3
                const int x0 = j << 2;              // 0,4,8,12

                float4 acc0 = wb4, acc1 = wb4, acc2 = wb4, acc3 = wb4;
                #pragma unroll
                for (int r = 0; r < 3; r++) {
                    const uint4* rowp = (const uint4*)&tile[y + r][0];
                    uint4 A = rowp[2 * j];          // cells x0-1, x0
                    uint4 B = rowp[2 * j + 1];      // cells x0+1, x0+2
                    uint4 C = rowp[2 * j + 2];      // cells x0+3, x0+4
                    float c6[6][4];
                    unpack_cell(A.x, A.y, c6[0]);
                    unpack_cell(A.z, A.w, c6[1]);
                    unpack_cell(B.x, B.y, c6[2]);
                    unpack_cell(B.z, B.w, c6[3]);
                    unpack_cell(C.x, C.y, c6[4]);
                    unpack_cell(C.z, C.w, c6[5]);
                    #pragma unroll
                    for (int kx = 0; kx < 3; kx++) {
                        const float4 wv = wtap[r * 3 + kx];   // broadcast LDS.128
                        acc0.x = fmaf(wv.x, c6[kx][0],     acc0.x);
                        acc0.y = fmaf(wv.y, c6[kx][1],     acc0.y);
                        acc0.z = fmaf(wv.z, c6[kx][2],     acc0.z);
                        acc0.w = fmaf(wv.w, c6[kx][3],     acc0.w);
                        acc1.x = fmaf(wv.x, c6[kx + 1][0], acc1.x);
                        acc1.y = fmaf(wv.y, c6[kx + 1][1], acc1.y);
                        acc1.z = fmaf(wv.z, c6[kx + 1][2], acc1.z);
                        acc1.w = fmaf(wv.w, c6[kx + 1][3], acc1.w);
                        acc2.x = fmaf(wv.x, c6[kx + 2][0], acc2.x);
                        acc2.y = fmaf(wv.y, c6[kx + 2][1], acc2.y);
                        acc2.z = fmaf(wv.z, c6[kx + 2][2], acc2.z);
                        acc2.w = fmaf(wv.w, c6[kx + 2][3], acc2.w);
                        acc3.x = fmaf(wv.x, c6[kx + 3][0], acc3.x);
                        acc3.y = fmaf(wv.y, c6[kx + 3][1], acc3.y);
                        acc3.z = fmaf(wv.z, c6[kx + 3][2], acc3.z);
                        acc3.w = fmaf(wv.w, c6[kx + 3][3], acc3.w);
                    }
                }
                const long long base = (long long)b * CELLS + y * HW + x0;
                out_p[base + 0] = wpf4.x * fmaxf(acc0.x, 0.f)
                                + wpf4.y * fmaxf(acc0.y, 0.f)
                                + wpf4.z * fmaxf(acc0.z, 0.f)
                                + wpf4.w * fmaxf(acc0.w, 0.f);
                out_p[base + 1] = wpf4.x * fmaxf(acc1.x, 0.f)
                                + wpf4.y * fmaxf(acc1.y, 0.f)
                                + wpf4.z * fmaxf(acc1.z, 0.f)
                                + wpf4.w * fmaxf(acc1.w, 0.f);
                out_p[base + 2] = wpf4.x * fmaxf(acc2.x, 0.f)
                                + wpf4.y * fmaxf(acc2.y, 0.f)
                                + wpf4.z * fmaxf(acc2.z, 0.f)
                                + wpf4.w * fmaxf(acc2.w, 0.f);
                if (j < 3) {                        // x0+3 = 15 invalid for j==3
                    out_p[base + 3] = wpf4.x * fmaxf(acc3.x, 0.f)
                                    + wpf4.y * fmaxf(acc3.y, 0.f)
                                    + wpf4.z * fmaxf(acc3.z, 0.f)
                                    + wpf4.w * fmaxf(acc3.w, 0.f);
                }
            }
        }

        // ---- value reduce (warp shuffles) + MLP on lane 0 ----
        #pragma unroll
        for (int off = 16; off > 0; off >>= 1) {
            v4 += __shfl_down_sync(0xffffffffu, v4, off);
            v5 += __shfl_down_sync(0xffffffffu, v5, off);
            v6 += __shfl_down_sync(0xffffffffu, v6, off);
            v7 += __shfl_down_sync(0xffffffffu, v7, off);
        }
        if (lane == 0) {
            const float4 l1b = __ldg((const float4*)l1_b);
            const float4 l2b = __ldg((const float4*)l2_b);
            float h[4], g[4];
            #pragma unroll
            for (int i = 0; i < 4; i++) {
                const float4 wv = __ldg((const float4*)(l1_w + i * 4));
                float a = ((const float*)&l1b)[i];
                a = fmaf(wv.x, v4, a); a = fmaf(wv.y, v5, a);
                a = fmaf(wv.z, v6, a); a = fmaf(wv.w, v7, a);
                h[i] = lrelu16(a);
            }
            #pragma unroll
            for (int i = 0; i < 4; i++) {
                const float4 wv = __ldg((const float4*)(l2_w + i * 4));
                float a = ((const float*)&l2b)[i];
                a = fmaf(wv.x, h[0], a); a = fmaf(wv.y, h[1], a);
                a = fmaf(wv.z, h[2], a); a = fmaf(wv.w, h[3], a);
                g[i] = lrelu16(a);
            }
            #pragma unroll
            for (int k = 0; k < 3; k++) {
                const float4 wv = __ldg((const float4*)(vf_w + k * 4));
                float a = __ldg(vf_b + k);
                a = fmaf(wv.x, g[0], a); a = fmaf(wv.y, g[1], a);
                a = fmaf(wv.z, g[2], a); a = fmaf(wv.w, g[3], a);
                out_v[(long long)b * 3 + k] = a;
            }
        }
        __syncwarp();     // conv reads done before next board overwrites tile
    }
}

extern "C" void kernel_launch(void* const* d_in, const int* in_sizes, int n_in,
                              void* d_out, int out_size) {
    const int*   sparse = (const int*)d_in[0];
    const int*   board  = (const int*)d_in[1];
    const float* W_emb  = (const float*)d_in[2];
    const float* dw_w   = (const float*)d_in[3];
    const float* dw_b   = (const float*)d_in[4];
    const float* pf_w   = (const float*)d_in[5];
    const float* l1_w   = (const float*)d_in[6];
    const float* l1_b   = (const float*)d_in[7];
    const float* l2_w   = (const float*)d_in[8];
    const float* l2_b   = (const float*)d_in[9];
    const float* vf_w   = (const float*)d_in[10];
    const float* vf_b   = (const float*)d_in[11];

    float* out   = (float*)d_out;
    float* out_v = out;                        // (B,3) first (tuple order)
    float* out_p = out + (size_t)BATCH * 3;    // (B,1,15,15) second

    emb_to_half_kernel<<<(NROWS * 2 + 255) / 256, 256>>>(W_emb);

    patnnue_kernel<<<GRID_P, 128>>>(sparse, board, dw_w, dw_b, pf_w,
                                    l1_w, l1_b, l2_w, l2_b, vf_w, vf_b,
                                    out_v, out_p);
}

// round 12
// speedup vs baseline: 1.0369x; 1.0369x over previous
#include <cuda_runtime.h>
#include <cuda_fp16.h>

#define BATCH 32768
#define HW 15
#define CELLS 225          // 15*15
#define PCODE 2380
#define NROWS (2 * (PCODE + 1))   // 4762 embedding rows
#define SMROW 17           // 15 + 2 halo
#define SMCOL 18           // padded (9 uint4 per row; col16 halo, col17 pad, both 0)
#define BLOCKS_PER_SM 9
#define GRID_P (148 * BLOCKS_PER_SM)   // 1332 persistent blocks
#define WARPS_PER_BLOCK 4
#define TOTAL_WARPS (GRID_P * WARPS_PER_BLOCK)

// fp16 embedding table: row = 8 halves = 16 bytes -> one LDG.128 per row
__device__ __align__(16) __half g_emb[NROWS * 8];

__global__ void __launch_bounds__(256)
emb_to_half_kernel(const float* __restrict__ W_emb) {
    int i = blockIdx.x * 256 + threadIdx.x;          // one half4 (4 floats) per thread
    if (i < NROWS * 2) {
        float4 f = __ldg((const float4*)(W_emb + (size_t)i * 4));
        __half2* dst = (__half2*)(g_emb + (size_t)i * 4);
        dst[0] = __floats2half2_rn(f.x, f.y);
        dst[1] = __floats2half2_rn(f.z, f.w);
    }
}

__device__ __forceinline__ float lrelu16(float x) {
    return x >= 0.f ? x : x * 0.0625f;
}

// acc += w * cell(lo,hi) elementwise over 4 channels
__device__ __forceinline__ void fma_cell(float4& acc, const float4 w,
                                         unsigned lo, unsigned hi) {
    float2 a = __half22float2(*(__half2*)&lo);
    float2 b = __half22float2(*(__half2*)&hi);
    acc.x = fmaf(w.x, a.x, acc.x);
    acc.y = fmaf(w.y, a.y, acc.y);
    acc.z = fmaf(w.z, b.x, acc.z);
    acc.w = fmaf(w.w, b.y, acc.w);
}

__global__ void __launch_bounds__(128, BLOCKS_PER_SM)
patnnue_kernel(const int* __restrict__ sparse,   // (B,12,15,15)
               const int* __restrict__ board,    // (B,2,15,15)
               const float* __restrict__ dw_w,   // (4,1,3,3)
               const float* __restrict__ dw_b,   // (4,)
               const float* __restrict__ pf_w,   // (1,4,1,1)
               const float* __restrict__ l1_w,   // (4,4)
               const float* __restrict__ l1_b,   // (4,)
               const float* __restrict__ l2_w,   // (4,4)
               const float* __restrict__ l2_b,   // (4,)
               const float* __restrict__ vf_w,   // (3,4)
               const float* __restrict__ vf_b,   // (3,)
               float* __restrict__ out_v,        // (B,3)
               float* __restrict__ out_p)        // (B,1,15,15)
{
    const int t    = threadIdx.x;
    const int w    = t >> 5;
    const int lane = t & 31;

    __shared__ __align__(16) uint2 feat_s[WARPS_PER_BLOCK][SMROW][SMCOL]; // per-warp tile
    __shared__ float pbuf[WARPS_PER_BLOCK][228];  // per-warp policy staging
    __shared__ float4 wtap[9];               // dw weights, tap-major across channels
    __shared__ float4 wb4;                   // dw_b
    __shared__ float4 wpf4;                  // pf_w

    // ---- one-time init: zero all tiles (halo stays zero forever) + weights ----
    uint2* fz = &feat_s[0][0][0];
    for (int i = t; i < WARPS_PER_BLOCK * SMROW * SMCOL; i += 128)
        fz[i] = make_uint2(0u, 0u);
    if (t < 36) {
        float wv = __ldg(dw_w + t);
        ((float*)&wtap[t % 9])[t / 9] = wv;  // transpose to tap-major
    } else if (t == 36) {
        wb4  = __ldg((const float4*)dw_b);
    } else if (t == 37) {
        wpf4 = __ldg((const float4*)pf_w);
    }
    __syncthreads();                          // the ONLY block-wide barrier

    // ---- kernel-constant PCODE rows (non-empty cells), hoisted out of loop ----
    uint2  cpol_pk;
    float4 cval;
    {
        uint4 e0 = __ldg((const uint4*)(g_emb + (size_t)PCODE * 8));
        uint4 e1 = __ldg((const uint4*)(g_emb + (size_t)(2 * PCODE + 1) * 8));
        float2 p01 = __half22float2(*(__half2*)&e0.x);
        float2 q01 = __half22float2(*(__half2*)&e1.x);
        float2 p23 = __half22float2(*(__half2*)&e0.y);
        float2 q23 = __half22float2(*(__half2*)&e1.y);
        float2 a45 = __half22float2(*(__half2*)&e0.z);
        float2 b45 = __half22float2(*(__half2*)&e1.z);
        float2 a67 = __half22float2(*(__half2*)&e0.w);
        float2 b67 = __half22float2(*(__half2*)&e1.w);
        __half2 hp0 = __floats2half2_rn(p01.x + q01.x, p01.y + q01.y);
        __half2 hp1 = __floats2half2_rn(p23.x + q23.x, p23.y + q23.y);
        cpol_pk = make_uint2(*(unsigned*)&hp0, *(unsigned*)&hp1);
        cval = make_float4(a45.x + b45.x, a45.y + b45.y, a67.x + b67.x, a67.y + b67.y);
    }

    uint2 (*tile)[SMCOL] = feat_s[w];
    float* pb = pbuf[w];
    const int gw = blockIdx.x * WARPS_PER_BLOCK + w;

    for (int b = gw; b < BATCH; b += TOTAL_WARPS) {
        const int* sp = sparse + (long long)b * (12 * CELLS);
        const int* bd = board  + (long long)b * (2 * CELLS);

        // ---- phase 1: gather, lane strides cells; only empty cells hit the table ----
        float v4 = 0.f, v5 = 0.f, v6 = 0.f, v7 = 0.f, cnt = 0.f;
        #pragma unroll
        for (int k = 0; k < 8; k++) {
            const int c = lane + 32 * k;
            if (c < CELLS) {
                const int i0 = __ldg(sp + 10 * CELLS + c);
                const int i1 = __ldg(sp + 11 * CELLS + c);
                const bool ne = (__ldg(bd + c) + __ldg(bd + CELLS + c)) > 0;
                uint2 pol;
                if (ne) {
                    pol = cpol_pk;
                    cnt += 1.f;
                } else {
                    uint4 e0 = __ldg((const uint4*)(g_emb + (size_t)i0 * 8));
                    uint4 e1 = __ldg((const uint4*)(g_emb + (size_t)(i1 + PCODE + 1) * 8));
                    float2 p01 = __half22float2(*(__half2*)&e0.x);
                    float2 q01 = __half22float2(*(__half2*)&e1.x);
                    float2 p23 = __half22float2(*(__half2*)&e0.y);
                    float2 q23 = __half22float2(*(__half2*)&e1.y);
                    float2 a45 = __half22float2(*(__half2*)&e0.z);
                    float2 b45 = __half22float2(*(__half2*)&e1.z);
                    float2 a67 = __half22float2(*(__half2*)&e0.w);
                    float2 b67 = __half22float2(*(__half2*)&e1.w);
                    __half2 hp0 = __floats2half2_rn(p01.x + q01.x, p01.y + q01.y);
                    __half2 hp1 = __floats2half2_rn(p23.x + q23.x, p23.y + q23.y);
                    pol = make_uint2(*(unsigned*)&hp0, *(unsigned*)&hp1);
                    v4 += a45.x + b45.x;
                    v5 += a45.y + b45.y;
                    v6 += a67.x + b67.x;
                    v7 += a67.y + b67.y;
                }
                tile[c / HW + 1][c % HW + 1] = pol;
            }
        }
        // fold the constant contribution of non-empty cells
        v4 = fmaf(cnt, cval.x, v4);
        v5 = fmaf(cnt, cval.y, v5);
        v6 = fmaf(cnt, cval.z, v6);
        v7 = fmaf(cnt, cval.w, v7);
        __syncwarp();

        // ---- phase 2: conv, 4 outputs/thread, unpack-on-demand (low regs) ----
        #pragma unroll
        for (int k = 0; k < 2; k++) {
            const int slot = lane + 32 * k;
            if (slot < 60) {
                const int y  = slot >> 2;           // 0..14
                const int j  = slot & 3;            // 0..3
                const int x0 = j << 2;              // 0,4,8,12

                float4 acc0 = wb4, acc1 = wb4, acc2 = wb4, acc3 = wb4;
                #pragma unroll
                for (int r = 0; r < 3; r++) {
                    const uint4* rowp = (const uint4*)&tile[y + r][0];
                    const uint4 A = rowp[2 * j];        // cells x0-1, x0
                    const uint4 B = rowp[2 * j + 1];    // cells x0+1, x0+2
                    const uint4 C = rowp[2 * j + 2];    // cells x0+3, x0+4
                    const float4 w0 = wtap[r * 3 + 0];
                    const float4 w1 = wtap[r * 3 + 1];
                    const float4 w2 = wtap[r * 3 + 2];
                    // cell m contributes to output o = m - kx via weight w_kx
                    fma_cell(acc0, w0, A.x, A.y);                       // m=0
                    fma_cell(acc1, w0, A.z, A.w);                       // m=1
                    fma_cell(acc0, w1, A.z, A.w);
                    fma_cell(acc2, w0, B.x, B.y);                       // m=2
                    fma_cell(acc1, w1, B.x, B.y);
                    fma_cell(acc0, w2, B.x, B.y);
                    fma_cell(acc3, w0, B.z, B.w);                       // m=3
                    fma_cell(acc2, w1, B.z, B.w);
                    fma_cell(acc1, w2, B.z, B.w);
                    fma_cell(acc3, w1, C.x, C.y);                       // m=4
                    fma_cell(acc2, w2, C.x, C.y);
                    fma_cell(acc3, w2, C.z, C.w);                       // m=5
                }
                const int base = y * HW + x0;
                pb[base + 0] = wpf4.x * fmaxf(acc0.x, 0.f)
                             + wpf4.y * fmaxf(acc0.y, 0.f)
                             + wpf4.z * fmaxf(acc0.z, 0.f)
                             + wpf4.w * fmaxf(acc0.w, 0.f);
                pb[base + 1] = wpf4.x * fmaxf(acc1.x, 0.f)
                             + wpf4.y * fmaxf(acc1.y, 0.f)
                             + wpf4.z * fmaxf(acc1.z, 0.f)
                             + wpf4.w * fmaxf(acc1.w, 0.f);
                pb[base + 2] = wpf4.x * fmaxf(acc2.x, 0.f)
                             + wpf4.y * fmaxf(acc2.y, 0.f)
                             + wpf4.z * fmaxf(acc2.z, 0.f)
                             + wpf4.w * fmaxf(acc2.w, 0.f);
                if (j < 3) {                        // x0+3 = 15 invalid for j==3
                    pb[base + 3] = wpf4.x * fmaxf(acc3.x, 0.f)
                                 + wpf4.y * fmaxf(acc3.y, 0.f)
                                 + wpf4.z * fmaxf(acc3.z, 0.f)
                                 + wpf4.w * fmaxf(acc3.w, 0.f);
                }
            }
        }
        __syncwarp();

        // ---- coalesced policy store: 8 contiguous STG.32 sweeps ----
        {
            float* dst = out_p + (long long)b * CELLS;
            #pragma unroll
            for (int k = 0; k < 8; k++) {
                const int c = lane + 32 * k;
                if (c < CELLS) dst[c] = pb[c];
            }
        }

        // ---- value reduce (warp shuffles) + MLP on lane 0 ----
        #pragma unroll
        for (int off = 16; off > 0; off >>= 1) {
            v4 += __shfl_down_sync(0xffffffffu, v4, off);
            v5 += __shfl_down_sync(0xffffffffu, v5, off);
            v6 += __shfl_down_sync(0xffffffffu, v6, off);
            v7 += __shfl_down_sync(0xffffffffu, v7, off);
        }
        if (lane == 0) {
            const float4 l1b = __ldg((const float4*)l1_b);
            const float4 l2b = __ldg((const float4*)l2_b);
            float h[4], g[4];
            #pragma unroll
            for (int i = 0; i < 4; i++) {
                const float4 wv = __ldg((const float4*)(l1_w + i * 4));
                float a = ((const float*)&l1b)[i];
                a = fmaf(wv.x, v4, a); a = fmaf(wv.y, v5, a);
                a = fmaf(wv.z, v6, a); a = fmaf(wv.w, v7, a);
                h[i] = lrelu16(a);
            }
            #pragma unroll
            for (int i = 0; i < 4; i++) {
                const float4 wv = __ldg((const float4*)(l2_w + i * 4));
                float a = ((const float*)&l2b)[i];
                a = fmaf(wv.x, h[0], a); a = fmaf(wv.y, h[1], a);
                a = fmaf(wv.z, h[2], a); a = fmaf(wv.w, h[3], a);
                g[i] = lrelu16(a);
            }
            #pragma unroll
            for (int k = 0; k < 3; k++) {
                const float4 wv = __ldg((const float4*)(vf_w + k * 4));
                float a = __ldg(vf_b + k);
                a = fmaf(wv.x, g[0], a); a = fmaf(wv.y, g[1], a);
                a = fmaf(wv.z, g[2], a); a = fmaf(wv.w, g[3], a);
                out_v[(long long)b * 3 + k] = a;
            }
        }
        __syncwarp();     // all reads done before next board overwrites tile/pbuf
    }
}

extern "C" void kernel_launch(void* const* d_in, const int* in_sizes, int n_in,
                              void* d_out, int out_size) {
    const int*   sparse = (const int*)d_in[0];
    const int*   board  = (const int*)d_in[1];
    const float* W_emb  = (const float*)d_in[2];
    const float* dw_w   = (const float*)d_in[3];
    const float* dw_b   = (const float*)d_in[4];
    const float* pf_w   = (const float*)d_in[5];
    const float* l1_w   = (const float*)d_in[6];
    const float* l1_b   = (const float*)d_in[7];
    const float* l2_w   = (const float*)d_in[8];
    const float* l2_b   = (const float*)d_in[9];
    const float* vf_w   = (const float*)d_in[10];
    const float* vf_b   = (const float*)d_in[11];

    float* out   = (float*)d_out;
    float* out_v = out;                        // (B,3) first (tuple order)
    float* out_p = out + (size_t)BATCH * 3;    // (B,1,15,15) second

    emb_to_half_kernel<<<(NROWS * 2 + 255) / 256, 256>>>(W_emb);

    patnnue_kernel<<<GRID_P, 128>>>(sparse, board, dw_w, dw_b, pf_w,
                                    l1_w, l1_b, l2_w, l2_b, vf_w, vf_b,
                                    out_v, out_p);
}

// round 13
// speedup vs baseline: 1.4552x; 1.4035x over previous
#include <cuda_runtime.h>
#include <cuda_fp16.h>

#define BATCH 32768
#define HW 15
#define CELLS 225          // 15*15
#define PCODE 2380
#define NROWS (2 * (PCODE + 1))   // 4762 embedding rows
#define SMROW 17           // 15 + 2 halo
#define SMCOL 18           // padded (9 uint4 per row; col16 halo, col17 pad, both 0)
#define GRID_P 1184        // 148 SMs * 8 resident blocks
#define WARPS_PER_BLOCK 4
#define TOTAL_WARPS (GRID_P * WARPS_PER_BLOCK)

// fp16 embedding table: row = 8 halves = 16 bytes -> one LDG.128 per row
__device__ __align__(16) __half g_emb[NROWS * 8];

__global__ void __launch_bounds__(256)
emb_to_half_kernel(const float* __restrict__ W_emb) {
    int i = blockIdx.x * 256 + threadIdx.x;          // one half4 (4 floats) per thread
    if (i < NROWS * 2) {
        float4 f = __ldg((const float4*)(W_emb + (size_t)i * 4));
        __half2* dst = (__half2*)(g_emb + (size_t)i * 4);
        dst[0] = __floats2half2_rn(f.x, f.y);
        dst[1] = __floats2half2_rn(f.z, f.w);
    }
}

__device__ __forceinline__ float lrelu16(float x) {
    return x >= 0.f ? x : x * 0.0625f;
}

__device__ __forceinline__ void unpack_cell(unsigned lo, unsigned hi, float* out) {
    float2 a = __half22float2(*(__half2*)&lo);
    float2 b = __half22float2(*(__half2*)&hi);
    out[0] = a.x; out[1] = a.y; out[2] = b.x; out[3] = b.y;
}

// gather one cell's two fp16 embedding rows.
// policy: fp16 adds (HADD2) — bitwise identical to fp32-add-then-round (IEEE).
// value: fp32 accumulation (precision-critical 225-term sum).
__device__ __forceinline__ void gather_cell(int r0, int r1, uint2* pol,
                                            float& v4, float& v5, float& v6, float& v7) {
    uint4 e0 = __ldg((const uint4*)(g_emb + (size_t)r0 * 8));
    uint4 e1 = __ldg((const uint4*)(g_emb + (size_t)r1 * 8));
    __half2 hp0 = __hadd2(*(__half2*)&e0.x, *(__half2*)&e1.x);
    __half2 hp1 = __hadd2(*(__half2*)&e0.y, *(__half2*)&e1.y);
    *pol = make_uint2(*(unsigned*)&hp0, *(unsigned*)&hp1);
    float2 a45 = __half22float2(*(__half2*)&e0.z);
    float2 b45 = __half22float2(*(__half2*)&e1.z);
    float2 a67 = __half22float2(*(__half2*)&e0.w);
    float2 b67 = __half22float2(*(__half2*)&e1.w);
    v4 += a45.x + b45.x;
    v5 += a45.y + b45.y;
    v6 += a67.x + b67.x;
    v7 += a67.y + b67.y;
}

__global__ void __launch_bounds__(128, 8)
patnnue_kernel(const int* __restrict__ sparse,   // (B,12,15,15)
               const int* __restrict__ board,    // (B,2,15,15)
               const float* __restrict__ dw_w,   // (4,1,3,3)
               const float* __restrict__ dw_b,   // (4,)
               const float* __restrict__ pf_w,   // (1,4,1,1)
               const float* __restrict__ l1_w,   // (4,4)
               const float* __restrict__ l1_b,   // (4,)
               const float* __restrict__ l2_w,   // (4,4)
               const float* __restrict__ l2_b,   // (4,)
               const float* __restrict__ vf_w,   // (3,4)
               const float* __restrict__ vf_b,   // (3,)
               float* __restrict__ out_v,        // (B,3)
               float* __restrict__ out_p)        // (B,1,15,15)
{
    const int t    = threadIdx.x;
    const int w    = t >> 5;
    const int lane = t & 31;

    __shared__ __align__(16) uint2 feat_s[WARPS_PER_BLOCK][SMROW][SMCOL]; // per-warp tile
    __shared__ float4 wtap[9];               // dw weights, tap-major across channels
    __shared__ float4 wb4;                   // dw_b
    __shared__ float4 wpf4;                  // pf_w

    // ---- one-time init: zero all tiles (halo stays zero forever) + weights ----
    uint2* fz = &feat_s[0][0][0];
    for (int i = t; i < WARPS_PER_BLOCK * SMROW * SMCOL; i += 128)
        fz[i] = make_uint2(0u, 0u);
    if (t < 36) {
        float wv = __ldg(dw_w + t);
        ((float*)&wtap[t % 9])[t / 9] = wv;  // transpose to tap-major
    } else if (t == 36) {
        wb4  = __ldg((const float4*)dw_b);
    } else if (t == 37) {
        wpf4 = __ldg((const float4*)pf_w);
    }
    __syncthreads();                          // the ONLY block-wide barrier

    uint2 (*tile)[SMCOL] = feat_s[w];
    const int gw = blockIdx.x * WARPS_PER_BLOCK + w;

    for (int b = gw; b < BATCH; b += TOTAL_WARPS) {
        const int* sp = sparse + (long long)b * (12 * CELLS);
        const int* bd = board  + (long long)b * (2 * CELLS);

        // ---- phase 1: gather, lane strides cells; 7 branchless iterations ----
        float v4 = 0.f, v5 = 0.f, v6 = 0.f, v7 = 0.f;
        #pragma unroll
        for (int k = 0; k < 7; k++) {
            const int c = lane + 32 * k;      // 0..223, always valid
            const int i0 = __ldg(sp + 10 * CELLS + c);
            const int i1 = __ldg(sp + 11 * CELLS + c);
            const bool ne = (__ldg(bd + c) + __ldg(bd + CELLS + c)) > 0;
            const int r0 = ne ? PCODE : i0;
            const int r1 = (ne ? PCODE : i1) + (PCODE + 1);
            uint2 pol;
            gather_cell(r0, r1, &pol, v4, v5, v6, v7);
            tile[c / HW + 1][c % HW + 1] = pol;
        }
        if (lane == 0) {                      // tail: cell 224
            const int c = 224;
            const int i0 = __ldg(sp + 10 * CELLS + c);
            const int i1 = __ldg(sp + 11 * CELLS + c);
            const bool ne = (__ldg(bd + c) + __ldg(bd + CELLS + c)) > 0;
            const int r0 = ne ? PCODE : i0;
            const int r1 = (ne ? PCODE : i1) + (PCODE + 1);
            uint2 pol;
            gather_cell(r0, r1, &pol, v4, v5, v6, v7);
            tile[15][15] = pol;               // c=224 -> y=14,x=14
        }
        __syncwarp();

        // ---- phase 2: conv, 4 output cells per thread (60 slots, 2 iterations) ----
        #pragma unroll
        for (int k = 0; k < 2; k++) {
            const int slot = lane + 32 * k;
            if (slot < 60) {
                const int y  = slot >> 2;           // 0..14
                const int j  = slot & 3;            // 0..3
                const int x0 = j << 2;              // 0,4,8,12

                float4 acc0 = wb4, acc1 = wb4, acc2 = wb4, acc3 = wb4;
                #pragma unroll
                for (int r = 0; r < 3; r++) {
                    const uint4* rowp = (const uint4*)&tile[y + r][0];
                    uint4 A = rowp[2 * j];          // cells x0-1, x0
                    uint4 B = rowp[2 * j + 1];      // cells x0+1, x0+2
                    uint4 C = rowp[2 * j + 2];      // cells x0+3, x0+4
                    float c6[6][4];
                    unpack_cell(A.x, A.y, c6[0]);
                    unpack_cell(A.z, A.w, c6[1]);
                    unpack_cell(B.x, B.y, c6[2]);
                    unpack_cell(B.z, B.w, c6[3]);
                    unpack_cell(C.x, C.y, c6[4]);
                    unpack_cell(C.z, C.w, c6[5]);
                    #pragma unroll
                    for (int kx = 0; kx < 3; kx++) {
                        const float4 wv = wtap[r * 3 + kx];   // broadcast LDS.128
                        acc0.x = fmaf(wv.x, c6[kx][0],     acc0.x);
                        acc0.y = fmaf(wv.y, c6[kx][1],     acc0.y);
                        acc0.z = fmaf(wv.z, c6[kx][2],     acc0.z);
                        acc0.w = fmaf(wv.w, c6[kx][3],     acc0.w);
                        acc1.x = fmaf(wv.x, c6[kx + 1][0], acc1.x);
                        acc1.y = fmaf(wv.y, c6[kx + 1][1], acc1.y);
                        acc1.z = fmaf(wv.z, c6[kx + 1][2], acc1.z);
                        acc1.w = fmaf(wv.w, c6[kx + 1][3], acc1.w);
                        acc2.x = fmaf(wv.x, c6[kx + 2][0], acc2.x);
                        acc2.y = fmaf(wv.y, c6[kx + 2][1], acc2.y);
                        acc2.z = fmaf(wv.z, c6[kx + 2][2], acc2.z);
                        acc2.w = fmaf(wv.w, c6[kx + 2][3], acc2.w);
                        acc3.x = fmaf(wv.x, c6[kx + 3][0], acc3.x);
                        acc3.y = fmaf(wv.y, c6[kx + 3][1], acc3.y);
                        acc3.z = fmaf(wv.z, c6[kx + 3][2], acc3.z);
                        acc3.w = fmaf(wv.w, c6[kx + 3][3], acc3.w);
                    }
                }
                const long long base = (long long)b * CELLS + y * HW + x0;
                out_p[base + 0] = wpf4.x * fmaxf(acc0.x, 0.f)
                                + wpf4.y * fmaxf(acc0.y, 0.f)
                                + wpf4.z * fmaxf(acc0.z, 0.f)
                                + wpf4.w * fmaxf(acc0.w, 0.f);
                out_p[base + 1] = wpf4.x * fmaxf(acc1.x, 0.f)
                                + wpf4.y * fmaxf(acc1.y, 0.f)
                                + wpf4.z * fmaxf(acc1.z, 0.f)
                                + wpf4.w * fmaxf(acc1.w, 0.f);
                out_p[base + 2] = wpf4.x * fmaxf(acc2.x, 0.f)
                                + wpf4.y * fmaxf(acc2.y, 0.f)
                                + wpf4.z * fmaxf(acc2.z, 0.f)
                                + wpf4.w * fmaxf(acc2.w, 0.f);
                if (j < 3) {                        // x0+3 = 15 invalid for j==3
                    out_p[base + 3] = wpf4.x * fmaxf(acc3.x, 0.f)
                                    + wpf4.y * fmaxf(acc3.y, 0.f)
                                    + wpf4.z * fmaxf(acc3.z, 0.f)
                                    + wpf4.w * fmaxf(acc3.w, 0.f);
                }
            }
        }

        // ---- value reduce (warp shuffles) + MLP on lane 0 ----
        #pragma unroll
        for (int off = 16; off > 0; off >>= 1) {
            v4 += __shfl_down_sync(0xffffffffu, v4, off);
            v5 += __shfl_down_sync(0xffffffffu, v5, off);
            v6 += __shfl_down_sync(0xffffffffu, v6, off);
            v7 += __shfl_down_sync(0xffffffffu, v7, off);
        }
        if (lane == 0) {
            const float4 l1b = __ldg((const float4*)l1_b);
            const float4 l2b = __ldg((const float4*)l2_b);
            float h[4], g[4];
            #pragma unroll
            for (int i = 0; i < 4; i++) {
                const float4 wv = __ldg((const float4*)(l1_w + i * 4));
                float a = ((const float*)&l1b)[i];
                a = fmaf(wv.x, v4, a); a = fmaf(wv.y, v5, a);
                a = fmaf(wv.z, v6, a); a = fmaf(wv.w, v7, a);
                h[i] = lrelu16(a);
            }
            #pragma unroll
            for (int i = 0; i < 4; i++) {
                const float4 wv = __ldg((const float4*)(l2_w + i * 4));
                float a = ((const float*)&l2b)[i];
                a = fmaf(wv.x, h[0], a); a = fmaf(wv.y, h[1], a);
                a = fmaf(wv.z, h[2], a); a = fmaf(wv.w, h[3], a);
                g[i] = lrelu16(a);
            }
            #pragma unroll
            for (int k = 0; k < 3; k++) {
                const float4 wv = __ldg((const float4*)(vf_w + k * 4));
                float a = __ldg(vf_b + k);
                a = fmaf(wv.x, g[0], a); a = fmaf(wv.y, g[1], a);
                a = fmaf(wv.z, g[2], a); a = fmaf(wv.w, g[3], a);
                out_v[(long long)b * 3 + k] = a;
            }
        }
        __syncwarp();     // conv reads done before next board overwrites tile
    }
}

extern "C" void kernel_launch(void* const* d_in, const int* in_sizes, int n_in,
                              void* d_out, int out_size) {
    const int*   sparse = (const int*)d_in[0];
    const int*   board  = (const int*)d_in[1];
    const float* W_emb  = (const float*)d_in[2];
    const float* dw_w   = (const float*)d_in[3];
    const float* dw_b   = (const float*)d_in[4];
    const float* pf_w   = (const float*)d_in[5];
    const float* l1_w   = (const float*)d_in[6];
    const float* l1_b   = (const float*)d_in[7];
    const float* l2_w   = (const float*)d_in[8];
    const float* l2_b   = (const float*)d_in[9];
    const float* vf_w   = (const float*)d_in[10];
    const float* vf_b   = (const float*)d_in[11];

    float* out   = (float*)d_out;
    float* out_v = out;                        // (B,3) first (tuple order)
    float* out_p = out + (size_t)BATCH * 3;    // (B,1,15,15) second

    emb_to_half_kernel<<<(NROWS * 2 + 255) / 256, 256>>>(W_emb);

    patnnue_kernel<<<GRID_P, 128>>>(sparse, board, dw_w, dw_b, pf_w,
                                    l1_w, l1_b, l2_w, l2_b, vf_w, vf_b,
                                    out_v, out_p);
}